// round 10
// baseline (speedup 1.0000x reference)
#include <cuda_runtime.h>
#include <cuda_bf16.h>

// GLoCELayerOutProp: B=4, T=1024, D=2048, N=8, S=8, H=8, ETA=1.
//
// R9: split the R8 monolith to break the smem+reg resource coupling:
//   k_prep : (grid 8)   pack [W|mu] -> bf16, muW, ||mu||^2      (~1.3us)
//   k_sel  : (grid 256) x-tile bf16 GEMM selector -> csel/ssel   (66KB smem)
//   k_apply: (grid 1024, 4 tok/blk) top-1 LoRA blend; x staged in 32KB smem,
//            ~60 regs -> 4 blocks/SM = 2x warp concurrency on the L1-heavy phase.

#define DD    2048
#define NCON  8
#define SR    8
#define HR    8
#define TBT   16            // tokens per k_sel block
#define AT    4             // tokens per k_apply block
#define NT    256
#define NWARP 8
#define NCOLS 72
#define YP    80
#define XBP   (DD + 8)

typedef unsigned int u32;

__device__ __nv_bfloat16 g_Wb[NCOLS * DD];
__device__ float g_muW[64];
__device__ float g_mun2[NCON];
__device__ int   g_csel[4096];
__device__ float g_ssel[4096];

__device__ __forceinline__ float warp_sum(float v) {
    #pragma unroll
    for (int o = 16; o > 0; o >>= 1) v += __shfl_xor_sync(0xffffffffu, v, o);
    return v;
}

// ---- prologue: grid 8 ----
__global__ void __launch_bounds__(256)
k_prep(const float* __restrict__ Wsel, const float* __restrict__ mu) {
    __shared__ float red[8][SR];
    __shared__ float redm[8];
    const int n = blockIdx.x;
    const int tid = threadIdx.x;
    const int warp = tid >> 5;
    const int lane = tid & 31;

    const float* Wn  = Wsel + (long)n * DD * SR;
    const float* mun = mu + n * DD;

    float acc[SR];
    #pragma unroll
    for (int s = 0; s < SR; s++) acc[s] = 0.f;
    float m2 = 0.f;

    #pragma unroll 2
    for (int it = 0; it < DD / 256; it++) {
        const int d = tid + 256 * it;
        const float mv = __ldg(mun + d);
        g_Wb[(64 + n) * DD + d] = __float2bfloat16_rn(mv);
        m2 = fmaf(mv, mv, m2);
        const float4 wa = __ldg(reinterpret_cast<const float4*>(Wn + (long)d * SR));
        const float4 wb = __ldg(reinterpret_cast<const float4*>(Wn + (long)d * SR + 4));
        g_Wb[(n * 8 + 0) * DD + d] = __float2bfloat16_rn(wa.x);
        g_Wb[(n * 8 + 1) * DD + d] = __float2bfloat16_rn(wa.y);
        g_Wb[(n * 8 + 2) * DD + d] = __float2bfloat16_rn(wa.z);
        g_Wb[(n * 8 + 3) * DD + d] = __float2bfloat16_rn(wa.w);
        g_Wb[(n * 8 + 4) * DD + d] = __float2bfloat16_rn(wb.x);
        g_Wb[(n * 8 + 5) * DD + d] = __float2bfloat16_rn(wb.y);
        g_Wb[(n * 8 + 6) * DD + d] = __float2bfloat16_rn(wb.z);
        g_Wb[(n * 8 + 7) * DD + d] = __float2bfloat16_rn(wb.w);
        acc[0] = fmaf(mv, wa.x, acc[0]);
        acc[1] = fmaf(mv, wa.y, acc[1]);
        acc[2] = fmaf(mv, wa.z, acc[2]);
        acc[3] = fmaf(mv, wa.w, acc[3]);
        acc[4] = fmaf(mv, wb.x, acc[4]);
        acc[5] = fmaf(mv, wb.y, acc[5]);
        acc[6] = fmaf(mv, wb.z, acc[6]);
        acc[7] = fmaf(mv, wb.w, acc[7]);
    }
    #pragma unroll
    for (int s = 0; s < SR; s++) {
        const float v = warp_sum(acc[s]);
        if (lane == 0) red[warp][s] = v;
    }
    m2 = warp_sum(m2);
    if (lane == 0) redm[warp] = m2;
    __syncthreads();
    if (tid < SR) {
        float s = 0.f;
        #pragma unroll
        for (int w = 0; w < 8; w++) s += red[w][tid];
        g_muW[n * 8 + tid] = s;
    }
    if (tid == 0) {
        float s = 0.f;
        #pragma unroll
        for (int w = 0; w < 8; w++) s += redm[w];
        g_mun2[n] = s;
    }
}

// ---- selector: grid 256, 16 tokens/block ----
__global__ void __launch_bounds__(NT, 2)
k_sel(const float* __restrict__ x,
      const float* __restrict__ center,
      const float* __restrict__ slope)
{
    extern __shared__ char dsm[];
    __nv_bfloat16* xb = reinterpret_cast<__nv_bfloat16*>(dsm);   // [TBT][XBP]
    float* ysum = reinterpret_cast<float*>(dsm);                 // aliases xb

    __shared__ float yfin[TBT][YP];
    __shared__ float nx2[TBT];
    __shared__ float gates[TBT][NCON];

    const int tid  = threadIdx.x;
    const int warp = tid >> 5;
    const int lane = tid & 31;
    const long tok0 = (long)blockIdx.x * TBT;

    // stage: warp w -> tokens 2w, 2w+1: fp32 -> bf16 smem, ||x||^2
    #pragma unroll
    for (int q = 0; q < 2; q++) {
        const int t = 2 * warp + q;
        const float4* xr = reinterpret_cast<const float4*>(x + (tok0 + t) * DD);
        float nrm = 0.f;
        #pragma unroll 4
        for (int i = 0; i < 16; i++) {
            const float4 v = __ldg(xr + i * 32 + lane);
            nrm = fmaf(v.x, v.x, nrm);
            nrm = fmaf(v.y, v.y, nrm);
            nrm = fmaf(v.z, v.z, nrm);
            nrm = fmaf(v.w, v.w, nrm);
            __nv_bfloat162 b0 = __float22bfloat162_rn(make_float2(v.x, v.y));
            __nv_bfloat162 b1 = __float22bfloat162_rn(make_float2(v.z, v.w));
            uint2 pk = make_uint2(*reinterpret_cast<u32*>(&b0),
                                  *reinterpret_cast<u32*>(&b1));
            *reinterpret_cast<uint2*>(&xb[t * XBP + i * 128 + lane * 4]) = pk;
        }
        nrm = warp_sum(nrm);
        if (lane == 0) nx2[t] = nrm;
    }
    __syncthreads();

    // GEMM: warp w -> K range [w*256, +256), 9 n-tiles
    {
        float d0a[9], d1a[9], d2a[9], d3a[9];
        #pragma unroll
        for (int j = 0; j < 9; j++) { d0a[j]=0.f; d1a[j]=0.f; d2a[j]=0.f; d3a[j]=0.f; }

        const int g = lane >> 2;
        const int c4 = lane & 3;

        #pragma unroll 1
        for (int kk = 0; kk < 16; kk++) {
            const int kbase = warp * 256 + kk * 16;
            const u32 a0 = *reinterpret_cast<const u32*>(&xb[g * XBP + kbase + 2 * c4]);
            const u32 a1 = *reinterpret_cast<const u32*>(&xb[(g + 8) * XBP + kbase + 2 * c4]);
            const u32 a2 = *reinterpret_cast<const u32*>(&xb[g * XBP + kbase + 2 * c4 + 8]);
            const u32 a3 = *reinterpret_cast<const u32*>(&xb[(g + 8) * XBP + kbase + 2 * c4 + 8]);
            #pragma unroll
            for (int j = 0; j < 9; j++) {
                const int col = j * 8 + g;
                const u32* bp = reinterpret_cast<const u32*>(g_Wb + col * DD + kbase);
                const u32 b0 = __ldg(bp + c4);
                const u32 b1 = __ldg(bp + c4 + 4);
                asm volatile(
                    "mma.sync.aligned.m16n8k16.row.col.f32.bf16.bf16.f32 "
                    "{%0,%1,%2,%3}, {%4,%5,%6,%7}, {%8,%9}, {%0,%1,%2,%3};"
                    : "+f"(d0a[j]), "+f"(d1a[j]), "+f"(d2a[j]), "+f"(d3a[j])
                    : "r"(a0), "r"(a1), "r"(a2), "r"(a3), "r"(b0), "r"(b1));
            }
        }
        __syncthreads();

        float* yw = ysum + warp * TBT * YP;
        #pragma unroll
        for (int j = 0; j < 9; j++) {
            const int cc = j * 8 + 2 * c4;
            *reinterpret_cast<float2*>(&yw[g * YP + cc])       = make_float2(d0a[j], d1a[j]);
            *reinterpret_cast<float2*>(&yw[(g + 8) * YP + cc]) = make_float2(d2a[j], d3a[j]);
        }
    }
    __syncthreads();

    // K-reduction
    #pragma unroll
    for (int i = 0; i < 5; i++) {
        const int o = tid + i * NT;
        const int t = o / YP, c = o % YP;
        float s = 0.f;
        #pragma unroll
        for (int w = 0; w < NWARP; w++) s += ysum[(w * TBT + t) * YP + c];
        yfin[t][c] = s;
    }
    __syncthreads();

    // scores + gates
    if (tid < TBT * NCON) {
        const int t = tid >> 3, n = tid & 7;
        const float xmu = yfin[t][64 + n];
        const float denom = nx2[t] - 2.f * xmu + g_mun2[n];
        float sc = 0.f;
        #pragma unroll
        for (int s = 0; s < SR; s++) {
            const float v = yfin[t][n * 8 + s] - g_muW[n * 8 + s];
            sc = fmaf(v, v, sc);
        }
        const float z = __ldg(slope + n) * (sc / denom - __ldg(center + n));
        gates[t][n] = 1.f / (1.f + __expf(-z));
    }
    __syncthreads();

    // argmax -> scratch
    if (tid < TBT) {
        float best = gates[tid][0];
        int bi = 0;
        #pragma unroll
        for (int n = 1; n < NCON; n++) {
            const float gv = gates[tid][n];
            if (gv > best) { best = gv; bi = n; }
        }
        g_csel[tok0 + tid] = bi;
        g_ssel[tok0 + tid] = best;
    }
}

// ---- apply: grid 1024, 4 tokens/block ----
__global__ void __launch_bounds__(NT, 4)
k_apply(const float* __restrict__ x,
        const float* __restrict__ upd,
        const float* __restrict__ dgn,
        const float* __restrict__ bias_w,
        const float* __restrict__ debias_w,
        float* __restrict__ out)
{
    __shared__ float xs[AT * DD];                 // 32 KB
    __shared__ float hpart[AT][NWARP][HR];
    __shared__ float hf_s[AT][HR];
    __shared__ int   csm[AT];
    __shared__ float ssm[AT];

    const int tid  = threadIdx.x;
    const int warp = tid >> 5;
    const int lane = tid & 31;
    const long tok0 = (long)blockIdx.x * AT;

    // stage x tile
    {
        const float4* xg = reinterpret_cast<const float4*>(x + tok0 * DD);
        float4* xs4 = reinterpret_cast<float4*>(xs);
        #pragma unroll 4
        for (int i = tid; i < AT * DD / 4; i += NT)
            xs4[i] = __ldg(xg + i);
    }
    if (tid < AT) {
        csm[tid] = g_csel[tok0 + tid];
        ssm[tid] = g_ssel[tok0 + tid];
    }
    __syncthreads();

    int sc4[AT];
    #pragma unroll
    for (int tt = 0; tt < AT; tt++) sc4[tt] = csm[tt];

    const int d0 = warp * (DD / NWARP);

    // h accumulation
    {
        float h[AT][HR];
        #pragma unroll
        for (int tt = 0; tt < AT; tt++)
            #pragma unroll
            for (int j = 0; j < HR; j++) h[tt][j] = 0.f;

        #pragma unroll 1
        for (int c = 0; c < NCON; c++) {
            bool any = false;
            #pragma unroll
            for (int tt = 0; tt < AT; tt++) any |= (sc4[tt] == c);
            if (!any) continue;

            const float* updc = upd + (long)c * DD * HR;
            const float* dbc  = debias_w + c * DD;
            #pragma unroll 2
            for (int i = 0; i < 8; i++) {
                const int d = d0 + lane + 32 * i;
                const float db = __ldg(dbc + d);
                const float4 ua = __ldg(reinterpret_cast<const float4*>(updc + (long)d * HR));
                const float4 ub = __ldg(reinterpret_cast<const float4*>(updc + (long)d * HR + 4));
                #pragma unroll
                for (int tt = 0; tt < AT; tt++) {
                    if (sc4[tt] == c) {
                        const float xd = xs[tt * DD + d] - db;
                        h[tt][0] = fmaf(ua.x, xd, h[tt][0]);
                        h[tt][1] = fmaf(ua.y, xd, h[tt][1]);
                        h[tt][2] = fmaf(ua.z, xd, h[tt][2]);
                        h[tt][3] = fmaf(ua.w, xd, h[tt][3]);
                        h[tt][4] = fmaf(ub.x, xd, h[tt][4]);
                        h[tt][5] = fmaf(ub.y, xd, h[tt][5]);
                        h[tt][6] = fmaf(ub.z, xd, h[tt][6]);
                        h[tt][7] = fmaf(ub.w, xd, h[tt][7]);
                    }
                }
            }
        }
        #pragma unroll
        for (int tt = 0; tt < AT; tt++) {
            #pragma unroll
            for (int j = 0; j < HR; j++) {
                const float v = warp_sum(h[tt][j]);
                if (lane == 0) hpart[tt][warp][j] = v;
            }
        }
    }
    __syncthreads();

    if (tid < AT * HR) {
        const int t = tid >> 3, j = tid & 7;
        float s = 0.f;
        #pragma unroll
        for (int w = 0; w < NWARP; w++) s += hpart[t][w][j];
        hf_s[t][j] = s;
    }
    __syncthreads();

    // output
    {
        float ss4[AT];
        float hf[AT][HR];
        #pragma unroll
        for (int tt = 0; tt < AT; tt++) {
            ss4[tt] = ssm[tt];
            #pragma unroll
            for (int j = 0; j < HR; j++) hf[tt][j] = hf_s[tt][j];
        }

        #pragma unroll 1
        for (int c = 0; c < NCON; c++) {
            bool any = false;
            #pragma unroll
            for (int tt = 0; tt < AT; tt++) any |= (sc4[tt] == c);
            if (!any) continue;

            const float* dgnc = dgn + (long)c * DD * HR;
            const float* bnc  = bias_w + c * DD;
            #pragma unroll 2
            for (int i = 0; i < 8; i++) {
                const int d = d0 + lane + 32 * i;
                const float bv = __ldg(bnc + d);
                const float4 ga = __ldg(reinterpret_cast<const float4*>(dgnc + (long)d * HR));
                const float4 gb = __ldg(reinterpret_cast<const float4*>(dgnc + (long)d * HR + 4));
                #pragma unroll
                for (int tt = 0; tt < AT; tt++) {
                    if (sc4[tt] == c) {
                        float dv = ga.x * hf[tt][0];
                        dv = fmaf(ga.y, hf[tt][1], dv);
                        dv = fmaf(ga.z, hf[tt][2], dv);
                        dv = fmaf(ga.w, hf[tt][3], dv);
                        dv = fmaf(gb.x, hf[tt][4], dv);
                        dv = fmaf(gb.y, hf[tt][5], dv);
                        dv = fmaf(gb.z, hf[tt][6], dv);
                        dv = fmaf(gb.w, hf[tt][7], dv);
                        const float s = ss4[tt];
                        out[(tok0 + tt) * DD + d] =
                            (1.f - s) * xs[tt * DD + d] + s * (bv + dv);
                    }
                }
            }
        }
    }
}

extern "C" void kernel_launch(void* const* d_in, const int* in_sizes, int n_in,
                              void* d_out, int out_size) {
    const float* x      = (const float*)d_in[0];
    const float* Wsel   = (const float*)d_in[1];
    const float* mu     = (const float*)d_in[2];
    const float* center = (const float*)d_in[3];
    const float* slope  = (const float*)d_in[4];
    const float* upd    = (const float*)d_in[5];
    const float* dgn    = (const float*)d_in[6];
    const float* bias_w = (const float*)d_in[7];
    const float* debias = (const float*)d_in[8];
    float* out = (float*)d_out;

    const int tokens = in_sizes[0] / DD;                        // 4096

    size_t smem_tile = (size_t)TBT * XBP * sizeof(__nv_bfloat16);
    size_t smem_ysum = (size_t)NWARP * TBT * YP * sizeof(float);
    size_t smem = smem_tile > smem_ysum ? smem_tile : smem_ysum;

    k_prep<<<NCON, 256>>>(Wsel, mu);

    cudaFuncSetAttribute(k_sel,
                         cudaFuncAttributeMaxDynamicSharedMemorySize, (int)smem);
    k_sel<<<tokens / TBT, NT, smem>>>(x, center, slope);

    k_apply<<<tokens / AT, NT>>>(x, upd, dgn, bias_w, debias, out);
}

// round 11
// speedup vs baseline: 1.0517x; 1.0517x over previous
#include <cuda_runtime.h>
#include <cuda_bf16.h>

// GLoCELayerOutProp: B=4, T=1024, D=2048, N=8, S=8, H=8, ETA=1.
//
// R10 = R8 monolith (bf16 MMA selector + coalesced phase 2; best: 57.8us)
//     + parallel prologue: grid 64 = (concept, 256-d chunk). Each block packs
//       its chunk of [W|mu] to bf16 and emits PARTIAL muW / ||mu||^2 sums;
//       the main kernel folds the 8 chunk-partials in-kernel (no atomics,
//       no extra launch). Fixes the 8-block latency-bound k_prep (8.2us ncu).

#define DD    2048
#define NCON  8
#define SR    8
#define HR    8
#define TBT   16
#define NT    256
#define NWARP 8
#define NCOLS 72
#define YP    80
#define XBP   (DD + 8)
#define NCHUNK 8            // prologue D-chunks

typedef unsigned int u32;

__device__ __nv_bfloat16 g_Wb[NCOLS * DD];     // [col][k]
__device__ float g_muWp[NCON][NCHUNK][SR];     // partial mu.W per chunk
__device__ float g_mun2p[NCON][NCHUNK];        // partial ||mu||^2 per chunk

__device__ __forceinline__ float warp_sum(float v) {
    #pragma unroll
    for (int o = 16; o > 0; o >>= 1) v += __shfl_xor_sync(0xffffffffu, v, o);
    return v;
}

// ---- prologue: grid 64 = 8 concepts x 8 chunks, 1 d per thread ----
__global__ void __launch_bounds__(256)
k_prep(const float* __restrict__ Wsel, const float* __restrict__ mu) {
    __shared__ float red[8][SR];
    __shared__ float redm[8];
    const int n     = blockIdx.x >> 3;
    const int chunk = blockIdx.x & 7;
    const int tid   = threadIdx.x;
    const int warp  = tid >> 5;
    const int lane  = tid & 31;
    const int d     = chunk * 256 + tid;

    const float mv = __ldg(mu + n * DD + d);
    const float4 wa = __ldg(reinterpret_cast<const float4*>(
                                Wsel + (long)n * DD * SR + (long)d * SR));
    const float4 wb = __ldg(reinterpret_cast<const float4*>(
                                Wsel + (long)n * DD * SR + (long)d * SR + 4));

    g_Wb[(64 + n) * DD + d]    = __float2bfloat16_rn(mv);
    g_Wb[(n * 8 + 0) * DD + d] = __float2bfloat16_rn(wa.x);
    g_Wb[(n * 8 + 1) * DD + d] = __float2bfloat16_rn(wa.y);
    g_Wb[(n * 8 + 2) * DD + d] = __float2bfloat16_rn(wa.z);
    g_Wb[(n * 8 + 3) * DD + d] = __float2bfloat16_rn(wa.w);
    g_Wb[(n * 8 + 4) * DD + d] = __float2bfloat16_rn(wb.x);
    g_Wb[(n * 8 + 5) * DD + d] = __float2bfloat16_rn(wb.y);
    g_Wb[(n * 8 + 6) * DD + d] = __float2bfloat16_rn(wb.z);
    g_Wb[(n * 8 + 7) * DD + d] = __float2bfloat16_rn(wb.w);

    float acc[SR];
    acc[0] = mv * wa.x;  acc[1] = mv * wa.y;
    acc[2] = mv * wa.z;  acc[3] = mv * wa.w;
    acc[4] = mv * wb.x;  acc[5] = mv * wb.y;
    acc[6] = mv * wb.z;  acc[7] = mv * wb.w;
    float m2 = mv * mv;

    #pragma unroll
    for (int s = 0; s < SR; s++) {
        const float v = warp_sum(acc[s]);
        if (lane == 0) red[warp][s] = v;
    }
    m2 = warp_sum(m2);
    if (lane == 0) redm[warp] = m2;
    __syncthreads();
    if (tid < SR) {
        float s = 0.f;
        #pragma unroll
        for (int w = 0; w < 8; w++) s += red[w][tid];
        g_muWp[n][chunk][tid] = s;
    }
    if (tid == 0) {
        float s = 0.f;
        #pragma unroll
        for (int w = 0; w < 8; w++) s += redm[w];
        g_mun2p[n][chunk] = s;
    }
}

// ---- main (R8 structure) ----
__global__ void __launch_bounds__(NT, 2)
gloce_main(const float* __restrict__ x,
           const float* __restrict__ center,
           const float* __restrict__ slope,
           const float* __restrict__ upd,
           const float* __restrict__ dgn,
           const float* __restrict__ bias_w,
           const float* __restrict__ debias_w,
           float* __restrict__ out)
{
    extern __shared__ char dsm[];
    __nv_bfloat16* xb = reinterpret_cast<__nv_bfloat16*>(dsm);   // [TBT][XBP]
    float* ysum = reinterpret_cast<float*>(dsm);                 // aliases xb

    __shared__ float yfin[TBT][YP];
    __shared__ float nx2[TBT];
    __shared__ float gates[TBT][NCON];
    __shared__ float ssel[TBT];
    __shared__ int   csel[TBT];
    __shared__ float hpart[TBT][NWARP][HR];
    __shared__ float hf_s[TBT][HR];
    __shared__ float s_muW[64];
    __shared__ float s_mun2[NCON];

    const int tid  = threadIdx.x;
    const int warp = tid >> 5;
    const int lane = tid & 31;
    const long tok0 = (long)blockIdx.x * TBT;

    // fold prologue partials (covered by the staging barrier)
    if (tid < 64) {
        const int n = tid >> 3, s = tid & 7;
        float v = 0.f;
        #pragma unroll
        for (int c = 0; c < NCHUNK; c++) v += g_muWp[n][c][s];
        s_muW[tid] = v;
    } else if (tid < 72) {
        const int n = tid - 64;
        float v = 0.f;
        #pragma unroll
        for (int c = 0; c < NCHUNK; c++) v += g_mun2p[n][c];
        s_mun2[n] = v;
    }

    // ---- stage: warp w -> tokens 2w, 2w+1: fp32 -> bf16 smem, ||x||^2 ----
    #pragma unroll
    for (int q = 0; q < 2; q++) {
        const int t = 2 * warp + q;
        const float4* xr = reinterpret_cast<const float4*>(x + (tok0 + t) * DD);
        float nrm = 0.f;
        #pragma unroll 4
        for (int i = 0; i < 16; i++) {
            const float4 v = __ldg(xr + i * 32 + lane);
            nrm = fmaf(v.x, v.x, nrm);
            nrm = fmaf(v.y, v.y, nrm);
            nrm = fmaf(v.z, v.z, nrm);
            nrm = fmaf(v.w, v.w, nrm);
            __nv_bfloat162 b0 = __float22bfloat162_rn(make_float2(v.x, v.y));
            __nv_bfloat162 b1 = __float22bfloat162_rn(make_float2(v.z, v.w));
            uint2 pk = make_uint2(*reinterpret_cast<u32*>(&b0),
                                  *reinterpret_cast<u32*>(&b1));
            *reinterpret_cast<uint2*>(&xb[t * XBP + i * 128 + lane * 4]) = pk;
        }
        nrm = warp_sum(nrm);
        if (lane == 0) nx2[t] = nrm;
    }
    __syncthreads();

    // ---- GEMM: warp w covers K range [w*256, +256), 9 n-tiles ----
    {
        float d0a[9], d1a[9], d2a[9], d3a[9];
        #pragma unroll
        for (int j = 0; j < 9; j++) { d0a[j]=0.f; d1a[j]=0.f; d2a[j]=0.f; d3a[j]=0.f; }

        const int g = lane >> 2;
        const int c4 = lane & 3;

        #pragma unroll 1
        for (int kk = 0; kk < 16; kk++) {
            const int kbase = warp * 256 + kk * 16;
            const u32 a0 = *reinterpret_cast<const u32*>(&xb[g * XBP + kbase + 2 * c4]);
            const u32 a1 = *reinterpret_cast<const u32*>(&xb[(g + 8) * XBP + kbase + 2 * c4]);
            const u32 a2 = *reinterpret_cast<const u32*>(&xb[g * XBP + kbase + 2 * c4 + 8]);
            const u32 a3 = *reinterpret_cast<const u32*>(&xb[(g + 8) * XBP + kbase + 2 * c4 + 8]);
            #pragma unroll
            for (int j = 0; j < 9; j++) {
                const int col = j * 8 + g;
                const u32* bp = reinterpret_cast<const u32*>(g_Wb + col * DD + kbase);
                const u32 b0 = __ldg(bp + c4);
                const u32 b1 = __ldg(bp + c4 + 4);
                asm volatile(
                    "mma.sync.aligned.m16n8k16.row.col.f32.bf16.bf16.f32 "
                    "{%0,%1,%2,%3}, {%4,%5,%6,%7}, {%8,%9}, {%0,%1,%2,%3};"
                    : "+f"(d0a[j]), "+f"(d1a[j]), "+f"(d2a[j]), "+f"(d3a[j])
                    : "r"(a0), "r"(a1), "r"(a2), "r"(a3), "r"(b0), "r"(b1));
            }
        }
        __syncthreads();

        float* yw = ysum + warp * TBT * YP;
        #pragma unroll
        for (int j = 0; j < 9; j++) {
            const int cc = j * 8 + 2 * c4;
            *reinterpret_cast<float2*>(&yw[g * YP + cc])       = make_float2(d0a[j], d1a[j]);
            *reinterpret_cast<float2*>(&yw[(g + 8) * YP + cc]) = make_float2(d2a[j], d3a[j]);
        }
    }
    __syncthreads();

    // ---- K-reduction ----
    #pragma unroll
    for (int i = 0; i < 5; i++) {
        const int o = tid + i * NT;
        const int t = o / YP, c = o % YP;
        float s = 0.f;
        #pragma unroll
        for (int w = 0; w < NWARP; w++) s += ysum[(w * TBT + t) * YP + c];
        yfin[t][c] = s;
    }
    __syncthreads();

    // ---- scores + gates ----
    if (tid < TBT * NCON) {
        const int t = tid >> 3, n = tid & 7;
        const float xmu = yfin[t][64 + n];
        const float denom = nx2[t] - 2.f * xmu + s_mun2[n];
        float sc = 0.f;
        #pragma unroll
        for (int s = 0; s < SR; s++) {
            const float v = yfin[t][n * 8 + s] - s_muW[n * 8 + s];
            sc = fmaf(v, v, sc);
        }
        const float z = __ldg(slope + n) * (sc / denom - __ldg(center + n));
        gates[t][n] = 1.f / (1.f + __expf(-z));
    }
    __syncthreads();

    if (tid < TBT) {
        float best = gates[tid][0];
        int bi = 0;
        #pragma unroll
        for (int n = 1; n < NCON; n++) {
            const float gv = gates[tid][n];
            if (gv > best) { best = gv; bi = n; }
        }
        ssel[tid] = best;
        csel[tid] = bi;
    }
    __syncthreads();

    // ---- phase 2: warp = 256-dim D-slice, coalesced ----
    const int d0 = warp * (DD / NWARP);

    #pragma unroll 1
    for (int g2 = 0; g2 < 4; g2++) {
        int sc4[4];
        #pragma unroll
        for (int tt = 0; tt < 4; tt++) sc4[tt] = csel[g2 * 4 + tt];

        float h[4][HR];
        #pragma unroll
        for (int tt = 0; tt < 4; tt++)
            #pragma unroll
            for (int j = 0; j < HR; j++) h[tt][j] = 0.f;

        #pragma unroll 1
        for (int c = 0; c < NCON; c++) {
            bool any = false;
            #pragma unroll
            for (int tt = 0; tt < 4; tt++) any |= (sc4[tt] == c);
            if (!any) continue;

            const float* updc = upd + (long)c * DD * HR;
            const float* dbc  = debias_w + c * DD;
            #pragma unroll 2
            for (int i = 0; i < 8; i++) {
                const int d = d0 + lane + 32 * i;
                const float db = __ldg(dbc + d);
                const float4 ua = __ldg(reinterpret_cast<const float4*>(updc + (long)d * HR));
                const float4 ub = __ldg(reinterpret_cast<const float4*>(updc + (long)d * HR + 4));
                #pragma unroll
                for (int tt = 0; tt < 4; tt++) {
                    if (sc4[tt] == c) {
                        const int t = g2 * 4 + tt;
                        const float xd = __ldg(x + (tok0 + t) * DD + d) - db;
                        h[tt][0] = fmaf(ua.x, xd, h[tt][0]);
                        h[tt][1] = fmaf(ua.y, xd, h[tt][1]);
                        h[tt][2] = fmaf(ua.z, xd, h[tt][2]);
                        h[tt][3] = fmaf(ua.w, xd, h[tt][3]);
                        h[tt][4] = fmaf(ub.x, xd, h[tt][4]);
                        h[tt][5] = fmaf(ub.y, xd, h[tt][5]);
                        h[tt][6] = fmaf(ub.z, xd, h[tt][6]);
                        h[tt][7] = fmaf(ub.w, xd, h[tt][7]);
                    }
                }
            }
        }
        #pragma unroll
        for (int tt = 0; tt < 4; tt++) {
            #pragma unroll
            for (int j = 0; j < HR; j++) {
                const float v = warp_sum(h[tt][j]);
                if (lane == 0) hpart[g2 * 4 + tt][warp][j] = v;
            }
        }
    }
    __syncthreads();

    if (tid < TBT * HR) {
        const int t = tid >> 3, j = tid & 7;
        float s = 0.f;
        #pragma unroll
        for (int w = 0; w < NWARP; w++) s += hpart[t][w][j];
        hf_s[t][j] = s;
    }
    __syncthreads();

    // ---- output ----
    #pragma unroll 1
    for (int g2 = 0; g2 < 4; g2++) {
        int   sc4[4];
        float ss4[4];
        float hf[4][HR];
        #pragma unroll
        for (int tt = 0; tt < 4; tt++) {
            sc4[tt] = csel[g2 * 4 + tt];
            ss4[tt] = ssel[g2 * 4 + tt];
            #pragma unroll
            for (int j = 0; j < HR; j++) hf[tt][j] = hf_s[g2 * 4 + tt][j];
        }

        #pragma unroll 1
        for (int c = 0; c < NCON; c++) {
            bool any = false;
            #pragma unroll
            for (int tt = 0; tt < 4; tt++) any |= (sc4[tt] == c);
            if (!any) continue;

            const float* dgnc = dgn + (long)c * DD * HR;
            const float* bnc  = bias_w + c * DD;
            #pragma unroll 2
            for (int i = 0; i < 8; i++) {
                const int d = d0 + lane + 32 * i;
                const float bv = __ldg(bnc + d);
                const float4 ga = __ldg(reinterpret_cast<const float4*>(dgnc + (long)d * HR));
                const float4 gb = __ldg(reinterpret_cast<const float4*>(dgnc + (long)d * HR + 4));
                #pragma unroll
                for (int tt = 0; tt < 4; tt++) {
                    if (sc4[tt] == c) {
                        const int t = g2 * 4 + tt;
                        float dv = ga.x * hf[tt][0];
                        dv = fmaf(ga.y, hf[tt][1], dv);
                        dv = fmaf(ga.z, hf[tt][2], dv);
                        dv = fmaf(ga.w, hf[tt][3], dv);
                        dv = fmaf(gb.x, hf[tt][4], dv);
                        dv = fmaf(gb.y, hf[tt][5], dv);
                        dv = fmaf(gb.z, hf[tt][6], dv);
                        dv = fmaf(gb.w, hf[tt][7], dv);
                        const float s = ss4[tt];
                        const float xv = __ldg(x + (tok0 + t) * DD + d);
                        out[(tok0 + t) * DD + d] = (1.f - s) * xv + s * (bv + dv);
                    }
                }
            }
        }
    }
}

extern "C" void kernel_launch(void* const* d_in, const int* in_sizes, int n_in,
                              void* d_out, int out_size) {
    const float* x      = (const float*)d_in[0];
    const float* Wsel   = (const float*)d_in[1];
    const float* mu     = (const float*)d_in[2];
    const float* center = (const float*)d_in[3];
    const float* slope  = (const float*)d_in[4];
    const float* upd    = (const float*)d_in[5];
    const float* dgn    = (const float*)d_in[6];
    const float* bias_w = (const float*)d_in[7];
    const float* debias = (const float*)d_in[8];
    float* out = (float*)d_out;

    const int tokens = in_sizes[0] / DD;                        // 4096
    const int grid   = tokens / TBT;                            // 256

    size_t smem_tile = (size_t)TBT * XBP * sizeof(__nv_bfloat16);
    size_t smem_ysum = (size_t)NWARP * TBT * YP * sizeof(float);
    size_t smem = smem_tile > smem_ysum ? smem_tile : smem_ysum;

    k_prep<<<NCON * NCHUNK, 256>>>(Wsel, mu);

    cudaFuncSetAttribute(gloce_main,
                         cudaFuncAttributeMaxDynamicSharedMemorySize, (int)smem);
    gloce_main<<<grid, NT, smem>>>(x, center, slope, upd, dgn, bias_w, debias, out);
}

// round 12
// speedup vs baseline: 1.3740x; 1.3064x over previous
#include <cuda_runtime.h>
#include <cuda_bf16.h>

// GLoCELayerOutProp: B=4, T=1024, D=2048, N=8, S=8, H=8, ETA=1.
//
// R11 = R10 + layout fixes for the two dominant L1 wavefront terms:
//  1. B matrix pre-packed in mma.m16n8k16 fragment order (Bfrag): GEMM B-load
//     = one coalesced uint2/lane (2 wf/req) instead of 8-line strided (8 wf).
//  2. upd/dgn pre-transposed to [n][j][d] fp32: phase-2 reads 8 coalesced
//     LDG.32/iter (8 wf) instead of 2 strided float4 (16 wf).
// All packing done in the grid-64 parallel prologue (one DRAM pass, ~2us).

#define DD    2048
#define NCON  8
#define SR    8
#define HR    8
#define TBT   16
#define NT    256
#define NWARP 8
#define YP    80
#define XBP   (DD + 8)
#define NCHUNK 8

typedef unsigned int u32;

// Bfrag: [w(8)][kk(16)][j(9)][lane(32)][bslot(2)] bf16x2  => 294912 bf16
__device__ __nv_bfloat16 g_Bf[8 * 16 * 9 * 32 * 2 * 2];
__device__ float g_updT[NCON][HR][DD];        // [n][j][d]
__device__ float g_dgnT[NCON][HR][DD];
__device__ float g_muWp[NCON][NCHUNK][SR];
__device__ float g_mun2p[NCON][NCHUNK];

__device__ __forceinline__ float warp_sum(float v) {
    #pragma unroll
    for (int o = 16; o > 0; o >>= 1) v += __shfl_xor_sync(0xffffffffu, v, o);
    return v;
}

// bf16 flat index in g_Bf for (col, k)
__device__ __forceinline__ int bf_idx(int col, int k) {
    const int w  = k >> 8;
    const int kk = (k & 255) >> 4;
    const int off = k & 15;
    const int bslot = off >> 3;
    const int c4 = (off & 7) >> 1;
    const int half = off & 1;
    const int g = col & 7;
    const int j = col >> 3;
    return ((((w * 16 + kk) * 9 + j) * 32 + (g * 4 + c4)) * 2 + bslot) * 2 + half;
}

// ---- prologue: grid 64 = 8 concepts x 8 chunks ----
__global__ void __launch_bounds__(256)
k_prep(const float* __restrict__ Wsel, const float* __restrict__ mu,
       const float* __restrict__ upd, const float* __restrict__ dgn) {
    __shared__ float red[8][SR];
    __shared__ float redm[8];
    const int n     = blockIdx.x >> 3;
    const int chunk = blockIdx.x & 7;
    const int tid   = threadIdx.x;
    const int warp  = tid >> 5;
    const int lane  = tid & 31;
    const int d     = chunk * 256 + tid;

    const float mv = __ldg(mu + n * DD + d);
    const float4 wa = __ldg(reinterpret_cast<const float4*>(
                                Wsel + (long)n * DD * SR + (long)d * SR));
    const float4 wb = __ldg(reinterpret_cast<const float4*>(
                                Wsel + (long)n * DD * SR + (long)d * SR + 4));

    // B fragments: W cols n*8+s, mu col 64+n
    g_Bf[bf_idx(n * 8 + 0, d)] = __float2bfloat16_rn(wa.x);
    g_Bf[bf_idx(n * 8 + 1, d)] = __float2bfloat16_rn(wa.y);
    g_Bf[bf_idx(n * 8 + 2, d)] = __float2bfloat16_rn(wa.z);
    g_Bf[bf_idx(n * 8 + 3, d)] = __float2bfloat16_rn(wa.w);
    g_Bf[bf_idx(n * 8 + 4, d)] = __float2bfloat16_rn(wb.x);
    g_Bf[bf_idx(n * 8 + 5, d)] = __float2bfloat16_rn(wb.y);
    g_Bf[bf_idx(n * 8 + 6, d)] = __float2bfloat16_rn(wb.z);
    g_Bf[bf_idx(n * 8 + 7, d)] = __float2bfloat16_rn(wb.w);
    g_Bf[bf_idx(64 + n,    d)] = __float2bfloat16_rn(mv);

    // transpose upd/dgn to [n][j][d]
    {
        const float4 ua = __ldg(reinterpret_cast<const float4*>(
                                    upd + (long)n * DD * HR + (long)d * HR));
        const float4 ub = __ldg(reinterpret_cast<const float4*>(
                                    upd + (long)n * DD * HR + (long)d * HR + 4));
        g_updT[n][0][d] = ua.x;  g_updT[n][1][d] = ua.y;
        g_updT[n][2][d] = ua.z;  g_updT[n][3][d] = ua.w;
        g_updT[n][4][d] = ub.x;  g_updT[n][5][d] = ub.y;
        g_updT[n][6][d] = ub.z;  g_updT[n][7][d] = ub.w;
        const float4 ga = __ldg(reinterpret_cast<const float4*>(
                                    dgn + (long)n * DD * HR + (long)d * HR));
        const float4 gb = __ldg(reinterpret_cast<const float4*>(
                                    dgn + (long)n * DD * HR + (long)d * HR + 4));
        g_dgnT[n][0][d] = ga.x;  g_dgnT[n][1][d] = ga.y;
        g_dgnT[n][2][d] = ga.z;  g_dgnT[n][3][d] = ga.w;
        g_dgnT[n][4][d] = gb.x;  g_dgnT[n][5][d] = gb.y;
        g_dgnT[n][6][d] = gb.z;  g_dgnT[n][7][d] = gb.w;
    }

    // muW / ||mu||^2 partials
    float acc[SR];
    acc[0] = mv * wa.x;  acc[1] = mv * wa.y;
    acc[2] = mv * wa.z;  acc[3] = mv * wa.w;
    acc[4] = mv * wb.x;  acc[5] = mv * wb.y;
    acc[6] = mv * wb.z;  acc[7] = mv * wb.w;
    float m2 = mv * mv;

    #pragma unroll
    for (int s = 0; s < SR; s++) {
        const float v = warp_sum(acc[s]);
        if (lane == 0) red[warp][s] = v;
    }
    m2 = warp_sum(m2);
    if (lane == 0) redm[warp] = m2;
    __syncthreads();
    if (tid < SR) {
        float s = 0.f;
        #pragma unroll
        for (int w = 0; w < 8; w++) s += red[w][tid];
        g_muWp[n][chunk][tid] = s;
    }
    if (tid == 0) {
        float s = 0.f;
        #pragma unroll
        for (int w = 0; w < 8; w++) s += redm[w];
        g_mun2p[n][chunk] = s;
    }
}

// ---- main ----
__global__ void __launch_bounds__(NT, 2)
gloce_main(const float* __restrict__ x,
           const float* __restrict__ center,
           const float* __restrict__ slope,
           const float* __restrict__ bias_w,
           const float* __restrict__ debias_w,
           float* __restrict__ out)
{
    extern __shared__ char dsm[];
    __nv_bfloat16* xb = reinterpret_cast<__nv_bfloat16*>(dsm);   // [TBT][XBP]
    float* ysum = reinterpret_cast<float*>(dsm);                 // aliases xb

    __shared__ float yfin[TBT][YP];
    __shared__ float nx2[TBT];
    __shared__ float gates[TBT][NCON];
    __shared__ float ssel[TBT];
    __shared__ int   csel[TBT];
    __shared__ float hpart[TBT][NWARP][HR];
    __shared__ float hf_s[TBT][HR];
    __shared__ float s_muW[64];
    __shared__ float s_mun2[NCON];

    const int tid  = threadIdx.x;
    const int warp = tid >> 5;
    const int lane = tid & 31;
    const long tok0 = (long)blockIdx.x * TBT;

    // fold prologue partials
    if (tid < 64) {
        const int n = tid >> 3, s = tid & 7;
        float v = 0.f;
        #pragma unroll
        for (int c = 0; c < NCHUNK; c++) v += g_muWp[n][c][s];
        s_muW[tid] = v;
    } else if (tid < 72) {
        const int n = tid - 64;
        float v = 0.f;
        #pragma unroll
        for (int c = 0; c < NCHUNK; c++) v += g_mun2p[n][c];
        s_mun2[n] = v;
    }

    // ---- stage x: warp w -> tokens 2w, 2w+1 ----
    #pragma unroll
    for (int q = 0; q < 2; q++) {
        const int t = 2 * warp + q;
        const float4* xr = reinterpret_cast<const float4*>(x + (tok0 + t) * DD);
        float nrm = 0.f;
        #pragma unroll 4
        for (int i = 0; i < 16; i++) {
            const float4 v = __ldg(xr + i * 32 + lane);
            nrm = fmaf(v.x, v.x, nrm);
            nrm = fmaf(v.y, v.y, nrm);
            nrm = fmaf(v.z, v.z, nrm);
            nrm = fmaf(v.w, v.w, nrm);
            __nv_bfloat162 b0 = __float22bfloat162_rn(make_float2(v.x, v.y));
            __nv_bfloat162 b1 = __float22bfloat162_rn(make_float2(v.z, v.w));
            uint2 pk = make_uint2(*reinterpret_cast<u32*>(&b0),
                                  *reinterpret_cast<u32*>(&b1));
            *reinterpret_cast<uint2*>(&xb[t * XBP + i * 128 + lane * 4]) = pk;
        }
        nrm = warp_sum(nrm);
        if (lane == 0) nx2[t] = nrm;
    }
    __syncthreads();

    // ---- GEMM: warp w -> K [w*256, +256); B from fragment-packed g_Bf ----
    {
        float d0a[9], d1a[9], d2a[9], d3a[9];
        #pragma unroll
        for (int j = 0; j < 9; j++) { d0a[j]=0.f; d1a[j]=0.f; d2a[j]=0.f; d3a[j]=0.f; }

        const int g = lane >> 2;
        const int c4 = lane & 3;
        const uint2* bf = reinterpret_cast<const uint2*>(g_Bf) +
                          (long)warp * 16 * 9 * 32 + lane;

        #pragma unroll 1
        for (int kk = 0; kk < 16; kk++) {
            const int kbase = warp * 256 + kk * 16;
            const u32 a0 = *reinterpret_cast<const u32*>(&xb[g * XBP + kbase + 2 * c4]);
            const u32 a1 = *reinterpret_cast<const u32*>(&xb[(g + 8) * XBP + kbase + 2 * c4]);
            const u32 a2 = *reinterpret_cast<const u32*>(&xb[g * XBP + kbase + 2 * c4 + 8]);
            const u32 a3 = *reinterpret_cast<const u32*>(&xb[(g + 8) * XBP + kbase + 2 * c4 + 8]);
            const uint2* bfk = bf + kk * 9 * 32;
            #pragma unroll
            for (int j = 0; j < 9; j++) {
                const uint2 bb = __ldg(bfk + j * 32);
                asm volatile(
                    "mma.sync.aligned.m16n8k16.row.col.f32.bf16.bf16.f32 "
                    "{%0,%1,%2,%3}, {%4,%5,%6,%7}, {%8,%9}, {%0,%1,%2,%3};"
                    : "+f"(d0a[j]), "+f"(d1a[j]), "+f"(d2a[j]), "+f"(d3a[j])
                    : "r"(a0), "r"(a1), "r"(a2), "r"(a3), "r"(bb.x), "r"(bb.y));
            }
        }
        __syncthreads();

        float* yw = ysum + warp * TBT * YP;
        #pragma unroll
        for (int j = 0; j < 9; j++) {
            const int cc = j * 8 + 2 * c4;
            *reinterpret_cast<float2*>(&yw[g * YP + cc])       = make_float2(d0a[j], d1a[j]);
            *reinterpret_cast<float2*>(&yw[(g + 8) * YP + cc]) = make_float2(d2a[j], d3a[j]);
        }
    }
    __syncthreads();

    // ---- K-reduction ----
    #pragma unroll
    for (int i = 0; i < 5; i++) {
        const int o = tid + i * NT;
        const int t = o / YP, c = o % YP;
        float s = 0.f;
        #pragma unroll
        for (int w = 0; w < NWARP; w++) s += ysum[(w * TBT + t) * YP + c];
        yfin[t][c] = s;
    }
    __syncthreads();

    // ---- scores + gates ----
    if (tid < TBT * NCON) {
        const int t = tid >> 3, n = tid & 7;
        const float xmu = yfin[t][64 + n];
        const float denom = nx2[t] - 2.f * xmu + s_mun2[n];
        float sc = 0.f;
        #pragma unroll
        for (int s = 0; s < SR; s++) {
            const float v = yfin[t][n * 8 + s] - s_muW[n * 8 + s];
            sc = fmaf(v, v, sc);
        }
        const float z = __ldg(slope + n) * (sc / denom - __ldg(center + n));
        gates[t][n] = 1.f / (1.f + __expf(-z));
    }
    __syncthreads();

    if (tid < TBT) {
        float best = gates[tid][0];
        int bi = 0;
        #pragma unroll
        for (int n = 1; n < NCON; n++) {
            const float gv = gates[tid][n];
            if (gv > best) { best = gv; bi = n; }
        }
        ssel[tid] = best;
        csel[tid] = bi;
    }
    __syncthreads();

    // ---- phase 2: warp = 256-dim D-slice; upd/dgn via transposed copies ----
    const int d0 = warp * (DD / NWARP);

    #pragma unroll 1
    for (int g2 = 0; g2 < 4; g2++) {
        int sc4[4];
        #pragma unroll
        for (int tt = 0; tt < 4; tt++) sc4[tt] = csel[g2 * 4 + tt];

        float h[4][HR];
        #pragma unroll
        for (int tt = 0; tt < 4; tt++)
            #pragma unroll
            for (int j = 0; j < HR; j++) h[tt][j] = 0.f;

        #pragma unroll 1
        for (int c = 0; c < NCON; c++) {
            bool any = false;
            #pragma unroll
            for (int tt = 0; tt < 4; tt++) any |= (sc4[tt] == c);
            if (!any) continue;

            const float* updT = &g_updT[c][0][0];
            const float* dbc  = debias_w + c * DD;
            #pragma unroll 2
            for (int i = 0; i < 8; i++) {
                const int d = d0 + lane + 32 * i;
                const float db = __ldg(dbc + d);
                float u[HR];
                #pragma unroll
                for (int j = 0; j < HR; j++) u[j] = __ldg(updT + j * DD + d);
                #pragma unroll
                for (int tt = 0; tt < 4; tt++) {
                    if (sc4[tt] == c) {
                        const int t = g2 * 4 + tt;
                        const float xd = __ldg(x + (tok0 + t) * DD + d) - db;
                        #pragma unroll
                        for (int j = 0; j < HR; j++)
                            h[tt][j] = fmaf(u[j], xd, h[tt][j]);
                    }
                }
            }
        }
        #pragma unroll
        for (int tt = 0; tt < 4; tt++) {
            #pragma unroll
            for (int j = 0; j < HR; j++) {
                const float v = warp_sum(h[tt][j]);
                if (lane == 0) hpart[g2 * 4 + tt][warp][j] = v;
            }
        }
    }
    __syncthreads();

    if (tid < TBT * HR) {
        const int t = tid >> 3, j = tid & 7;
        float s = 0.f;
        #pragma unroll
        for (int w = 0; w < NWARP; w++) s += hpart[t][w][j];
        hf_s[t][j] = s;
    }
    __syncthreads();

    // ---- output ----
    #pragma unroll 1
    for (int g2 = 0; g2 < 4; g2++) {
        int   sc4[4];
        float ss4[4];
        float hf[4][HR];
        #pragma unroll
        for (int tt = 0; tt < 4; tt++) {
            sc4[tt] = csel[g2 * 4 + tt];
            ss4[tt] = ssel[g2 * 4 + tt];
            #pragma unroll
            for (int j = 0; j < HR; j++) hf[tt][j] = hf_s[g2 * 4 + tt][j];
        }

        #pragma unroll 1
        for (int c = 0; c < NCON; c++) {
            bool any = false;
            #pragma unroll
            for (int tt = 0; tt < 4; tt++) any |= (sc4[tt] == c);
            if (!any) continue;

            const float* dgnT = &g_dgnT[c][0][0];
            const float* bnc  = bias_w + c * DD;
            #pragma unroll 2
            for (int i = 0; i < 8; i++) {
                const int d = d0 + lane + 32 * i;
                const float bv = __ldg(bnc + d);
                float gv[HR];
                #pragma unroll
                for (int j = 0; j < HR; j++) gv[j] = __ldg(dgnT + j * DD + d);
                #pragma unroll
                for (int tt = 0; tt < 4; tt++) {
                    if (sc4[tt] == c) {
                        const int t = g2 * 4 + tt;
                        float dv = gv[0] * hf[tt][0];
                        #pragma unroll
                        for (int j = 1; j < HR; j++)
                            dv = fmaf(gv[j], hf[tt][j], dv);
                        const float s = ss4[tt];
                        const float xv = __ldg(x + (tok0 + t) * DD + d);
                        out[(tok0 + t) * DD + d] = (1.f - s) * xv + s * (bv + dv);
                    }
                }
            }
        }
    }
}

extern "C" void kernel_launch(void* const* d_in, const int* in_sizes, int n_in,
                              void* d_out, int out_size) {
    const float* x      = (const float*)d_in[0];
    const float* Wsel   = (const float*)d_in[1];
    const float* mu     = (const float*)d_in[2];
    const float* center = (const float*)d_in[3];
    const float* slope  = (const float*)d_in[4];
    const float* upd    = (const float*)d_in[5];
    const float* dgn    = (const float*)d_in[6];
    const float* bias_w = (const float*)d_in[7];
    const float* debias = (const float*)d_in[8];
    float* out = (float*)d_out;

    const int tokens = in_sizes[0] / DD;                        // 4096
    const int grid   = tokens / TBT;                            // 256

    size_t smem_tile = (size_t)TBT * XBP * sizeof(__nv_bfloat16);
    size_t smem_ysum = (size_t)NWARP * TBT * YP * sizeof(float);
    size_t smem = smem_tile > smem_ysum ? smem_tile : smem_ysum;

    k_prep<<<NCON * NCHUNK, 256>>>(Wsel, mu, upd, dgn);

    cudaFuncSetAttribute(gloce_main,
                         cudaFuncAttributeMaxDynamicSharedMemorySize, (int)smem);
    gloce_main<<<grid, NT, smem>>>(x, center, slope, bias_w, debias, out);
}